// round 12
// baseline (speedup 1.0000x reference)
#include <cuda_runtime.h>
#include <cuda_bf16.h>

// ---------------------------------------------------------------------------
// MS-SSIM loss, 3 scales, 11x11 separable Gaussian (sigma=1.5), zero padding.
// R11: R10 (width-4 horizontal items, bf16x2 (u,v) tile, origin x0-8) with
//      SPITCH 48 -> 50 (row stride = 2 mod 4 words: phase-3 LDS.64 becomes
//      bank-conflict-free, 4 -> 2 wavefronts) and 7 blocks/SM.
// ---------------------------------------------------------------------------

#define TILE   32
#define HALO   5
#define LDIM   42            // TILE + 2*HALO
#define SPITCH 50            // raw tile pitch (bf16x2 units), origin x0-8

__device__ constexpr float GWC[11] = {
    0.00102838f, 0.00759875f, 0.03600077f, 0.10936069f, 0.21300553f,
    0.26601173f, 0.21300553f, 0.10936069f, 0.03600077f, 0.00759875f,
    0.00102838f
};

#define C1_ 0.0001f
#define C2_ 0.0009f

typedef unsigned long long u64;

__device__ __forceinline__ u64 pack2(float a, float b) {
    u64 r; asm("mov.b64 %0, {%1, %2};" : "=l"(r) : "f"(a), "f"(b)); return r;
}
__device__ __forceinline__ void unpack2(u64 v, float& a, float& b) {
    asm("mov.b64 {%0, %1}, %2;" : "=f"(a), "=f"(b) : "l"(v));
}
__device__ __forceinline__ u64 fma2(u64 a, u64 b, u64 c) {
    u64 d; asm("fma.rn.f32x2 %0, %1, %2, %3;" : "=l"(d) : "l"(a), "l"(b), "l"(c)); return d;
}
__device__ __forceinline__ u64 mul2(u64 a, u64 b) {
    u64 d; asm("mul.rn.f32x2 %0, %1, %2;" : "=l"(d) : "l"(a), "l"(b)); return d;
}
// bf16x2 -> two fp32 via pure bit ops (exact)
__device__ __forceinline__ void bf2dec(unsigned v, float& a, float& b) {
    a = __int_as_float((int)(v << 16));
    b = __int_as_float((int)(v & 0xffff0000u));
}

// Pooled pyramids (device globals), bf16x2 storing (u, v) = (p+t, p-t)
__device__ __nv_bfloat162 g_s1[64 * 256 * 256];
__device__ __nv_bfloat162 g_s2[64 * 128 * 128];
__device__ double g_acc[3];   // zero-initialized at load; reset by finalize

// ---------------------------------------------------------------------------
// Phases 3-5. Tile x-origin is x0-8: output col c taps smem cols c+3..c+13.
// Width-4 item (r, c0=4g): needs cols c0+3..c0+16, read as 8 LDS.64 covering
// cols c0+2..c0+17 (local q=0..15; q=1..14 used). Output o uses q=o+1..o+11
// with weight w[q-o-1].
// ---------------------------------------------------------------------------
__device__ __forceinline__ void phases345(
    __nv_bfloat162 (&sxy)[LDIM][SPITCH],
    ulonglong2 (&pAB)[LDIM][TILE],
    float (&red)[8],
    int tx, int ty, int tid, int sidx)
{
    u64 wp[11];
    #pragma unroll
    for (int k = 0; k < 11; k++) wp[k] = pack2(GWC[k], GWC[k]);

    // ---- horizontal blur: 336 items x 4 outputs ----
    #pragma unroll
    for (int it = 0; it < 2; it++) {
        const int i = tid + it * 256;
        if (i < 336) {
            const int r = i >> 3;
            const int g = i & 7;                 // c0 = 4g
            const uint2* row64 = (const uint2*)&sxy[r][0];
            const int base = 2 * g + 1;          // uint2 idx of cols c0+2,c0+3
            u64 hA[4] = {0, 0, 0, 0};
            u64 hB[4] = {0, 0, 0, 0};
            #pragma unroll
            for (int m = 0; m < 8; m++) {
                uint2 pq = row64[base + m];
                #pragma unroll
                for (int h = 0; h < 2; h++) {
                    const int q = 2 * m + h;
                    if (q >= 1 && q <= 14) {
                        unsigned v = h ? pq.y : pq.x;
                        float a, b; bf2dec(v, a, b);
                        u64 p  = pack2(a, b);
                        u64 sq = mul2(p, p);
                        #pragma unroll
                        for (int o = 0; o < 4; o++) {
                            const int w = q - o - 1;
                            if (w >= 0 && w < 11) {
                                hA[o] = fma2(p,  wp[w], hA[o]);
                                hB[o] = fma2(sq, wp[w], hB[o]);
                            }
                        }
                    }
                }
            }
            #pragma unroll
            for (int o = 0; o < 4; o++)
                pAB[r][4 * g + o] = make_ulonglong2(hA[o], hB[o]);
        }
    }
    __syncthreads();

    // ---- vertical blur + SSIM: 4 output rows per thread, 1 col ----
    u64 mA[4] = {0, 0, 0, 0};   // (mu_u, mu_v)
    u64 mB[4] = {0, 0, 0, 0};   // (E[u^2], E[v^2])
    const int rbase = ty * 4;
    #pragma unroll
    for (int k = 0; k < 14; k++) {
        const int hr = rbase + k;
        ulonglong2 vab = pAB[hr][tx];          // LDS.128
        #pragma unroll
        for (int j = 0; j < 4; j++) {
            const int kk = k - j;
            if (kk >= 0 && kk < 11) {
                mA[j] = fma2(vab.x, wp[kk], mA[j]);
                mB[j] = fma2(vab.y, wp[kk], mB[j]);
            }
        }
    }

    float acc = 0.0f;
    #pragma unroll
    for (int j = 0; j < 4; j++) {
        u64 m2 = mul2(mA[j], mA[j]);           // (mu_u^2, mu_v^2)
        float m2u, m2v; unpack2(m2, m2u, m2v);
        float eu, ev;   unpack2(mB[j], eu, ev);
        float D1 = m2u - m2v;                  // = 4*mu1*mu2
        float S1 = m2u + m2v;                  // = 2*(mu1^2+mu2^2)
        float DE = eu - ev;                    // = 4*E[xy]
        float SE = eu + ev;                    // = 2*(E[x^2]+E[y^2])
        float num = (0.5f * D1 + C1_) * (0.5f * (DE - D1) + C2_);
        float den = (0.5f * S1 + C1_) * (0.5f * (SE - S1) + C2_);
        acc += __fdividef(num, den);
    }

    #pragma unroll
    for (int o = 16; o > 0; o >>= 1)
        acc += __shfl_down_sync(0xffffffffu, acc, o);
    if ((tid & 31) == 0) red[tid >> 5] = acc;
    __syncthreads();
    if (tid < 8) {
        float v = red[tid];
        #pragma unroll
        for (int o = 4; o > 0; o >>= 1)
            v += __shfl_down_sync(0xffu, v, o, 8);
        if (tid == 0) atomicAdd(&g_acc[sidx], (double)v);
    }
}

// ---------------------------------------------------------------------------
// Scale 0: fp32 global inputs -> (u,v) bf16x2 tile; writes BOTH pooled
// pyramids; then SSIM.
// ---------------------------------------------------------------------------
__global__ __launch_bounds__(256, 7)
void ssim_scale0_kernel(const float* __restrict__ pin, const float* __restrict__ tin)
{
    __shared__ __nv_bfloat162 sxy[LDIM][SPITCH];
    __shared__ ulonglong2 pAB[LDIM][TILE];
    __shared__ float red[8];

    const int tx = threadIdx.x, ty = threadIdx.y;
    const int tid = ty * 32 + tx;
    const int x0 = blockIdx.x * TILE;
    const int y0 = blockIdx.y * TILE;
    const int H = 512, W = 512;
    const long imgBase = (long)blockIdx.z * H * W;

    const bool interior = (x0 >= 8) && (x0 + 40 <= W) &&
                          (y0 >= 8) && (y0 + 40 <= H);
    if (interior) {
        // 42 rows x 12 float4 loads = cols 0..47 (phase 3 reads <= col 45,
        // pools read <= col 39; cols 48-49 unused). Gmem 16B-aligned.
        const float* pb = pin + imgBase + (long)(y0 - 5) * W + (x0 - 8);
        const float* tb = tin + imgBase + (long)(y0 - 5) * W + (x0 - 8);
        #pragma unroll
        for (int it = 0; it < 2; it++) {
            const int i = tid + it * 256;
            if (i < 504) {
                const int r = i / 12, c4 = i - r * 12;
                float4 av = __ldg((const float4*)(pb + (long)r * W) + c4);
                float4 bv = __ldg((const float4*)(tb + (long)r * W) + c4);
                __nv_bfloat162 t0 = __floats2bfloat162_rn(av.x + bv.x, av.x - bv.x);
                __nv_bfloat162 t1 = __floats2bfloat162_rn(av.y + bv.y, av.y - bv.y);
                __nv_bfloat162 t2 = __floats2bfloat162_rn(av.z + bv.z, av.z - bv.z);
                __nv_bfloat162 t3 = __floats2bfloat162_rn(av.w + bv.w, av.w - bv.w);
                // rows are 8B-aligned (200B pitch): two ST.64
                *(uint2*)&sxy[r][4 * c4] =
                    make_uint2(*(unsigned*)&t0, *(unsigned*)&t1);
                *(uint2*)&sxy[r][4 * c4 + 2] =
                    make_uint2(*(unsigned*)&t2, *(unsigned*)&t3);
            }
        }
    } else {
        #pragma unroll
        for (int i = tid; i < LDIM * SPITCH; i += 256) {
            int r = i / SPITCH, c = i - r * SPITCH;
            int gy = y0 + r - 5;
            int gx = x0 + c - 8;
            float a = 0.0f, b = 0.0f;
            if (gy >= 0 && gy < H && gx >= 0 && gx < W) {
                long off = imgBase + (long)gy * W + gx;
                a = __ldg(pin + off);
                b = __ldg(tin + off);
            }
            sxy[r][c] = __floats2bfloat162_rn(a + b, a - b);
        }
    }
    __syncthreads();

    // 2x2 pool -> g_s1 (pooling is linear in (u,v))
    {
        const int pr = tid >> 4;
        const int pc = tid & 15;
        const int r = 5 + 2 * pr, c = 8 + 2 * pc;
        float u0, v0, u1, v1, u2, v2, u3, v3;
        bf2dec(*(const unsigned*)&sxy[r][c],         u0, v0);
        bf2dec(*(const unsigned*)&sxy[r][c + 1],     u1, v1);
        bf2dec(*(const unsigned*)&sxy[r + 1][c],     u2, v2);
        bf2dec(*(const unsigned*)&sxy[r + 1][c + 1], u3, v3);
        float u = 0.25f * (u0 + u1 + u2 + u3);
        float v = 0.25f * (v0 + v1 + v2 + v3);
        long poff = (long)blockIdx.z * 256 * 256
                  + (long)(y0 / 2 + pr) * 256 + (x0 / 2 + pc);
        g_s1[poff] = __floats2bfloat162_rn(u, v);
    }
    // 4x4 pool -> g_s2 (threads 0..63)
    if (tid < 64) {
        const int pr = tid >> 3;
        const int pc = tid & 7;
        const int r = 5 + 4 * pr, c = 8 + 4 * pc;
        float su = 0.f, sv = 0.f;
        #pragma unroll
        for (int dr = 0; dr < 4; dr++)
            #pragma unroll
            for (int dc = 0; dc < 4; dc++) {
                float u, v;
                bf2dec(*(const unsigned*)&sxy[r + dr][c + dc], u, v);
                su += u; sv += v;
            }
        long poff = (long)blockIdx.z * 128 * 128
                  + (long)(y0 / 4 + pr) * 128 + (x0 / 4 + pc);
        g_s2[poff] = __floats2bfloat162_rn(su * 0.0625f, sv * 0.0625f);
    }

    phases345(sxy, pAB, red, tx, ty, tid, 0);
}

// ---------------------------------------------------------------------------
// Scales 1+2 merged: z < 64 -> scale1 (256x256), z >= 64 -> scale2 (128x128).
// ---------------------------------------------------------------------------
__global__ __launch_bounds__(256, 7)
void ssim_small_kernel()
{
    __shared__ __nv_bfloat162 sxy[LDIM][SPITCH];
    __shared__ ulonglong2 pAB[LDIM][TILE];
    __shared__ float red[8];

    const int tx = threadIdx.x, ty = threadIdx.y;
    const int tid = ty * 32 + tx;
    const int z = blockIdx.z;

    const __nv_bfloat162* src;
    int x0, y0, img, H, sidx;
    if (z < 64) {
        src = g_s1; H = 256; sidx = 1;
        x0 = blockIdx.x * TILE; y0 = blockIdx.y * TILE; img = z;
    } else {
        src = g_s2; H = 128; sidx = 2;
        const int z2 = z - 64;
        img = z2 * 4 + ((blockIdx.y >> 2) << 1) + (blockIdx.x >> 2);
        x0 = (blockIdx.x & 3) * TILE;
        y0 = (blockIdx.y & 3) * TILE;
    }
    const int W = H;
    const long imgBase = (long)img * H * W;

    const bool interior = (x0 >= 8) && (x0 + 40 <= W) &&
                          (y0 >= 8) && (y0 + 40 <= H);
    if (interior) {
        const __nv_bfloat162* sb = src + imgBase + (long)(y0 - 5) * W + (x0 - 8);
        #pragma unroll
        for (int it = 0; it < 2; it++) {
            const int i = tid + it * 256;
            if (i < 504) {
                const int r = i / 12, c4 = i - r * 12;
                uint4 v = __ldg((const uint4*)(sb + (long)r * W) + c4);
                *(uint2*)&sxy[r][4 * c4]     = make_uint2(v.x, v.y);
                *(uint2*)&sxy[r][4 * c4 + 2] = make_uint2(v.z, v.w);
            }
        }
    } else {
        #pragma unroll
        for (int i = tid; i < LDIM * SPITCH; i += 256) {
            int r = i / SPITCH, c = i - r * SPITCH;
            int gy = y0 + r - 5;
            int gx = x0 + c - 8;
            __nv_bfloat162 v; *(unsigned*)&v = 0u;
            if (gy >= 0 && gy < H && gx >= 0 && gx < W)
                v = __ldg(src + imgBase + (long)gy * W + gx);
            sxy[r][c] = v;
        }
    }
    __syncthreads();

    phases345(sxy, pAB, red, tx, ty, tid, sidx);
}

__global__ void finalize_kernel(float* __restrict__ out) {
    const double n0 = 64.0 * 512.0 * 512.0;
    const double n1 = 64.0 * 256.0 * 256.0;
    const double n2 = 64.0 * 128.0 * 128.0;
    double ms = 0.5 * (g_acc[0] / n0) + 0.3 * (g_acc[1] / n1) + 0.2 * (g_acc[2] / n2);
    out[0] = (float)(1.0 - ms);
    // reset for the next graph replay (globals start zeroed at module load)
    g_acc[0] = 0.0; g_acc[1] = 0.0; g_acc[2] = 0.0;
}

extern "C" void kernel_launch(void* const* d_in, const int* in_sizes, int n_in,
                              void* d_out, int out_size)
{
    const float* pred = (const float*)d_in[0];
    const float* targ = (const float*)d_in[1];
    float* out = (float*)d_out;

    dim3 blk(32, 8);
    ssim_scale0_kernel<<<dim3(16, 16, 64), blk>>>(pred, targ);
    ssim_small_kernel<<<dim3(8, 8, 80), blk>>>();
    finalize_kernel<<<1, 1>>>(out);
}

// round 13
// speedup vs baseline: 1.0113x; 1.0113x over previous
#include <cuda_runtime.h>
#include <cuda_bf16.h>

// ---------------------------------------------------------------------------
// MS-SSIM loss, 3 scales, 11x11 separable Gaussian (sigma=1.5), zero padding.
// R12: R7 base (width-2 horizontal items, bf16x2 (u,v) tile, SPITCH 44,
//      7 blocks/SM) + channel-split vertical pass: lane pairs split A/B
//      halves (LDS.64 x18 instead of LDS.128 x14 -> phase-4 wavefronts -36%),
//      SSIM inputs reassembled with 4 xor-1 shuffles.
// ---------------------------------------------------------------------------

#define TILE   32
#define HALO   5
#define LDIM   42            // TILE + 2*HALO
#define SPITCH 44            // raw tile pitch (bf16x2 units), origin x0-6

__device__ constexpr float GWC[11] = {
    0.00102838f, 0.00759875f, 0.03600077f, 0.10936069f, 0.21300553f,
    0.26601173f, 0.21300553f, 0.10936069f, 0.03600077f, 0.00759875f,
    0.00102838f
};

#define C1_ 0.0001f
#define C2_ 0.0009f

typedef unsigned long long u64;

__device__ __forceinline__ u64 pack2(float a, float b) {
    u64 r; asm("mov.b64 %0, {%1, %2};" : "=l"(r) : "f"(a), "f"(b)); return r;
}
__device__ __forceinline__ void unpack2(u64 v, float& a, float& b) {
    asm("mov.b64 {%0, %1}, %2;" : "=f"(a), "=f"(b) : "l"(v));
}
__device__ __forceinline__ u64 fma2(u64 a, u64 b, u64 c) {
    u64 d; asm("fma.rn.f32x2 %0, %1, %2, %3;" : "=l"(d) : "l"(a), "l"(b), "l"(c)); return d;
}
__device__ __forceinline__ u64 mul2(u64 a, u64 b) {
    u64 d; asm("mul.rn.f32x2 %0, %1, %2;" : "=l"(d) : "l"(a), "l"(b)); return d;
}
// bf16x2 -> two fp32 via pure bit ops (exact)
__device__ __forceinline__ void bf2dec(unsigned v, float& a, float& b) {
    a = __int_as_float((int)(v << 16));
    b = __int_as_float((int)(v & 0xffff0000u));
}
// 64-bit xor-1 shuffle (two 32-bit shuffles)
__device__ __forceinline__ u64 shflx1_64(u64 v) {
    unsigned lo = (unsigned)v, hi = (unsigned)(v >> 32);
    lo = __shfl_xor_sync(0xffffffffu, lo, 1);
    hi = __shfl_xor_sync(0xffffffffu, hi, 1);
    return ((u64)hi << 32) | lo;
}

// Pooled pyramids (device globals), bf16x2 storing (u, v) = (p+t, p-t)
__device__ __nv_bfloat162 g_s1[64 * 256 * 256];
__device__ __nv_bfloat162 g_s2[64 * 128 * 128];
__device__ double g_acc[3];   // zero-initialized at load; reset by finalize

// ---------------------------------------------------------------------------
// Phases 3-5. Tile x-origin is x0-6: output col c taps sxy cols c+1..c+11.
// Phase 3: 672 width-2 items (R7). Phase 4: channel-split — even lanes
// accumulate the A (mu) half, odd lanes the B (E) half, 8 output rows each,
// via LDS.64; SSIM reassembled with xor-1 shuffles.
// ---------------------------------------------------------------------------
__device__ __forceinline__ void phases345(
    __nv_bfloat162 (&sxy)[LDIM][SPITCH],
    ulonglong2 (&pAB)[LDIM][TILE],
    float (&red)[8],
    int tx, int ty, int tid, int sidx)
{
    u64 wp[11];
    #pragma unroll
    for (int k = 0; k < 11; k++) wp[k] = pack2(GWC[k], GWC[k]);

    // ---- horizontal blur: 672 items x 2 outputs (R7) ----
    #pragma unroll
    for (int it = 0; it < 3; it++) {
        const int i = tid + it * 256;
        if (i < 672) {
            const int r  = i >> 4;
            const int cb = i & 15;                       // pair base c0 = 2*cb
            const uint2* row64 = (const uint2*)&sxy[r][0];
            u64 hA0 = 0, hB0 = 0, hA1 = 0, hB1 = 0;
            #pragma unroll
            for (int m = 0; m < 7; m++) {
                uint2 pq = row64[cb + m];
                #pragma unroll
                for (int h = 0; h < 2; h++) {
                    const int j = 2 * m + h;
                    if (j >= 1 && j <= 12) {
                        unsigned v = h ? pq.y : pq.x;
                        float a, b; bf2dec(v, a, b);
                        u64 p  = pack2(a, b);
                        u64 sq = mul2(p, p);
                        if (j <= 11) {
                            hA0 = fma2(p,  wp[j - 1], hA0);
                            hB0 = fma2(sq, wp[j - 1], hB0);
                        }
                        if (j >= 2) {
                            hA1 = fma2(p,  wp[j - 2], hA1);
                            hB1 = fma2(sq, wp[j - 2], hB1);
                        }
                    }
                }
            }
            pAB[r][2 * cb]     = make_ulonglong2(hA0, hB0);
            pAB[r][2 * cb + 1] = make_ulonglong2(hA1, hB1);
        }
    }
    __syncthreads();

    // ---- vertical blur, channel-split: 8 rows x 1 col x 1 half/thread ----
    const int ch  = tid & 1;            // 0: A (mu-pair), 1: B (E-pair)
    const int col = (tid >> 1) & 31;
    const int rg  = tid >> 6;           // 0..3, 8 output rows each
    const int rbase = rg * 8;

    u64 m[8] = {0, 0, 0, 0, 0, 0, 0, 0};
    const char* pbase = (const char*)&pAB[rbase][col] + ch * 8;
    #pragma unroll
    for (int k = 0; k < 18; k++) {
        u64 val = *(const u64*)(pbase + (long)k * (TILE * 16));  // LDS.64
        #pragma unroll
        for (int j = 0; j < 8; j++) {
            const int kk = k - j;
            if (kk >= 0 && kk < 11)
                m[j] = fma2(val, wp[kk], m[j]);
        }
    }

    // ---- SSIM: exchange halves within xor-1 lane pairs ----
    // even lane computes rows rbase+0..3 (has A, needs B)
    // odd  lane computes rows rbase+4..7 (has B, needs A)
    float acc = 0.0f;
    #pragma unroll
    for (int j = 0; j < 4; j++) {
        u64 send  = ch ? m[j] : m[j + 4];
        u64 other = shflx1_64(send);
        u64 mAj = ch ? other    : m[j];
        u64 mBj = ch ? m[j + 4] : other;
        u64 m2 = mul2(mAj, mAj);              // (mu_u^2, mu_v^2)
        float m2u, m2v; unpack2(m2, m2u, m2v);
        float eu, ev;   unpack2(mBj, eu, ev);
        float D1 = m2u - m2v;                 // = 4*mu1*mu2
        float S1 = m2u + m2v;                 // = 2*(mu1^2+mu2^2)
        float DE = eu - ev;                   // = 4*E[xy]
        float SE = eu + ev;                   // = 2*(E[x^2]+E[y^2])
        float num = (0.5f * D1 + C1_) * (0.5f * (DE - D1) + C2_);
        float den = (0.5f * S1 + C1_) * (0.5f * (SE - S1) + C2_);
        acc += __fdividef(num, den);
    }

    #pragma unroll
    for (int o = 16; o > 0; o >>= 1)
        acc += __shfl_down_sync(0xffffffffu, acc, o);
    if ((tid & 31) == 0) red[tid >> 5] = acc;
    __syncthreads();
    if (tid < 8) {
        float v = red[tid];
        #pragma unroll
        for (int o = 4; o > 0; o >>= 1)
            v += __shfl_down_sync(0xffu, v, o, 8);
        if (tid == 0) atomicAdd(&g_acc[sidx], (double)v);
    }
}

// ---------------------------------------------------------------------------
// Scale 0: fp32 global inputs -> (u,v) bf16x2 tile; writes BOTH pooled
// pyramids; then SSIM.
// ---------------------------------------------------------------------------
__global__ __launch_bounds__(256, 7)
void ssim_scale0_kernel(const float* __restrict__ pin, const float* __restrict__ tin)
{
    __shared__ __nv_bfloat162 sxy[LDIM][SPITCH];
    __shared__ ulonglong2 pAB[LDIM][TILE];
    __shared__ float red[8];

    const int tx = threadIdx.x, ty = threadIdx.y;
    const int tid = ty * 32 + tx;
    const int x0 = blockIdx.x * TILE;
    const int y0 = blockIdx.y * TILE;
    const int H = 512, W = 512;
    const long imgBase = (long)blockIdx.z * H * W;

    const bool interior = (x0 >= 8) && (x0 + 40 <= W) &&
                          (y0 >= 8) && (y0 + 40 <= H);
    if (interior) {
        // 42 rows x 22 float2 loads (x origin x0-6, 8B aligned)
        const float* pb = pin + imgBase + (long)(y0 - 5) * W + (x0 - 6);
        const float* tb = tin + imgBase + (long)(y0 - 5) * W + (x0 - 6);
        #pragma unroll
        for (int it = 0; it < 4; it++) {
            const int i = tid + it * 256;
            if (i < 924) {
                const int r = i / 22, c2 = i - r * 22;
                float2 av = __ldg((const float2*)(pb + (long)r * W) + c2);
                float2 bv = __ldg((const float2*)(tb + (long)r * W) + c2);
                __nv_bfloat162 t0 = __floats2bfloat162_rn(av.x + bv.x, av.x - bv.x);
                __nv_bfloat162 t1 = __floats2bfloat162_rn(av.y + bv.y, av.y - bv.y);
                *(uint2*)&sxy[r][2 * c2] =
                    make_uint2(*(unsigned*)&t0, *(unsigned*)&t1);
            }
        }
    } else {
        #pragma unroll
        for (int i = tid; i < LDIM * SPITCH; i += 256) {
            int r = i / SPITCH, c = i - r * SPITCH;
            int gy = y0 + r - 5;
            int gx = x0 + c - 6;
            float a = 0.0f, b = 0.0f;
            if (gy >= 0 && gy < H && gx >= 0 && gx < W) {
                long off = imgBase + (long)gy * W + gx;
                a = __ldg(pin + off);
                b = __ldg(tin + off);
            }
            sxy[r][c] = __floats2bfloat162_rn(a + b, a - b);
        }
    }
    __syncthreads();

    // 2x2 pool -> g_s1 (pooling is linear in (u,v))
    {
        const int pr = tid >> 4;
        const int pc = tid & 15;
        const int r = 5 + 2 * pr, c = 6 + 2 * pc;
        float u0, v0, u1, v1, u2, v2, u3, v3;
        bf2dec(*(const unsigned*)&sxy[r][c],         u0, v0);
        bf2dec(*(const unsigned*)&sxy[r][c + 1],     u1, v1);
        bf2dec(*(const unsigned*)&sxy[r + 1][c],     u2, v2);
        bf2dec(*(const unsigned*)&sxy[r + 1][c + 1], u3, v3);
        float u = 0.25f * (u0 + u1 + u2 + u3);
        float v = 0.25f * (v0 + v1 + v2 + v3);
        long poff = (long)blockIdx.z * 256 * 256
                  + (long)(y0 / 2 + pr) * 256 + (x0 / 2 + pc);
        g_s1[poff] = __floats2bfloat162_rn(u, v);
    }
    // 4x4 pool -> g_s2 (threads 0..63)
    if (tid < 64) {
        const int pr = tid >> 3;
        const int pc = tid & 7;
        const int r = 5 + 4 * pr, c = 6 + 4 * pc;
        float su = 0.f, sv = 0.f;
        #pragma unroll
        for (int dr = 0; dr < 4; dr++)
            #pragma unroll
            for (int dc = 0; dc < 4; dc++) {
                float u, v;
                bf2dec(*(const unsigned*)&sxy[r + dr][c + dc], u, v);
                su += u; sv += v;
            }
        long poff = (long)blockIdx.z * 128 * 128
                  + (long)(y0 / 4 + pr) * 128 + (x0 / 4 + pc);
        g_s2[poff] = __floats2bfloat162_rn(su * 0.0625f, sv * 0.0625f);
    }

    phases345(sxy, pAB, red, tx, ty, tid, 0);
}

// ---------------------------------------------------------------------------
// Scales 1+2 merged: z < 64 -> scale1 (256x256), z >= 64 -> scale2 (128x128).
// ---------------------------------------------------------------------------
__global__ __launch_bounds__(256, 7)
void ssim_small_kernel()
{
    __shared__ __nv_bfloat162 sxy[LDIM][SPITCH];
    __shared__ ulonglong2 pAB[LDIM][TILE];
    __shared__ float red[8];

    const int tx = threadIdx.x, ty = threadIdx.y;
    const int tid = ty * 32 + tx;
    const int z = blockIdx.z;

    const __nv_bfloat162* src;
    int x0, y0, img, H, sidx;
    if (z < 64) {
        src = g_s1; H = 256; sidx = 1;
        x0 = blockIdx.x * TILE; y0 = blockIdx.y * TILE; img = z;
    } else {
        src = g_s2; H = 128; sidx = 2;
        const int z2 = z - 64;
        img = z2 * 4 + ((blockIdx.y >> 2) << 1) + (blockIdx.x >> 2);
        x0 = (blockIdx.x & 3) * TILE;
        y0 = (blockIdx.y & 3) * TILE;
    }
    const int W = H;
    const long imgBase = (long)img * H * W;

    const bool interior = (x0 >= 8) && (x0 + 40 <= W) &&
                          (y0 >= 8) && (y0 + 40 <= H);
    if (interior) {
        const __nv_bfloat162* sb = src + imgBase + (long)(y0 - 5) * W + (x0 - 6);
        #pragma unroll
        for (int it = 0; it < 4; it++) {
            const int i = tid + it * 256;
            if (i < 924) {
                const int r = i / 22, c2 = i - r * 22;
                uint2 v = __ldg((const uint2*)(sb + (long)r * W) + c2);
                *(uint2*)&sxy[r][2 * c2] = v;
            }
        }
    } else {
        #pragma unroll
        for (int i = tid; i < LDIM * SPITCH; i += 256) {
            int r = i / SPITCH, c = i - r * SPITCH;
            int gy = y0 + r - 5;
            int gx = x0 + c - 6;
            __nv_bfloat162 v; *(unsigned*)&v = 0u;
            if (gy >= 0 && gy < H && gx >= 0 && gx < W)
                v = __ldg(src + imgBase + (long)gy * W + gx);
            sxy[r][c] = v;
        }
    }
    __syncthreads();

    phases345(sxy, pAB, red, tx, ty, tid, sidx);
}

__global__ void finalize_kernel(float* __restrict__ out) {
    const double n0 = 64.0 * 512.0 * 512.0;
    const double n1 = 64.0 * 256.0 * 256.0;
    const double n2 = 64.0 * 128.0 * 128.0;
    double ms = 0.5 * (g_acc[0] / n0) + 0.3 * (g_acc[1] / n1) + 0.2 * (g_acc[2] / n2);
    out[0] = (float)(1.0 - ms);
    // reset for the next graph replay (globals start zeroed at module load)
    g_acc[0] = 0.0; g_acc[1] = 0.0; g_acc[2] = 0.0;
}

extern "C" void kernel_launch(void* const* d_in, const int* in_sizes, int n_in,
                              void* d_out, int out_size)
{
    const float* pred = (const float*)d_in[0];
    const float* targ = (const float*)d_in[1];
    float* out = (float*)d_out;

    dim3 blk(32, 8);
    ssim_scale0_kernel<<<dim3(16, 16, 64), blk>>>(pred, targ);
    ssim_small_kernel<<<dim3(8, 8, 80), blk>>>();
    finalize_kernel<<<1, 1>>>(out);
}

// round 14
// speedup vs baseline: 1.0667x; 1.0547x over previous
#include <cuda_runtime.h>
#include <cuda_bf16.h>

// ---------------------------------------------------------------------------
// MS-SSIM loss, 3 scales, 11x11 separable Gaussian (sigma=1.5), zero padding.
// R13: R7 champion structure exactly (width-2 items, bf16x2 (u,v) tile,
//      SPITCH 44, 7 blocks/SM) + ZERO-PADDED pyramid layout:
//      g_s1 270x266, g_s2 142x138 (pads never written -> stay zero) so every
//      small-scale block takes the vectorized interior loader; border branch
//      removed from the small kernel.
// ---------------------------------------------------------------------------

#define TILE   32
#define HALO   5
#define LDIM   42            // TILE + 2*HALO
#define SPITCH 44            // raw tile pitch (bf16x2 units), origin x0-6

// padded pyramid dims: left pad 6, right pad 8, top/bottom pad 5
#define PW1 270
#define PH1 266
#define PW2 142
#define PH2 138

__device__ constexpr float GWC[11] = {
    0.00102838f, 0.00759875f, 0.03600077f, 0.10936069f, 0.21300553f,
    0.26601173f, 0.21300553f, 0.10936069f, 0.03600077f, 0.00759875f,
    0.00102838f
};

#define C1_ 0.0001f
#define C2_ 0.0009f

typedef unsigned long long u64;

__device__ __forceinline__ u64 pack2(float a, float b) {
    u64 r; asm("mov.b64 %0, {%1, %2};" : "=l"(r) : "f"(a), "f"(b)); return r;
}
__device__ __forceinline__ void unpack2(u64 v, float& a, float& b) {
    asm("mov.b64 {%0, %1}, %2;" : "=f"(a), "=f"(b) : "l"(v));
}
__device__ __forceinline__ u64 fma2(u64 a, u64 b, u64 c) {
    u64 d; asm("fma.rn.f32x2 %0, %1, %2, %3;" : "=l"(d) : "l"(a), "l"(b), "l"(c)); return d;
}
__device__ __forceinline__ u64 mul2(u64 a, u64 b) {
    u64 d; asm("mul.rn.f32x2 %0, %1, %2;" : "=l"(d) : "l"(a), "l"(b)); return d;
}
// bf16x2 -> two fp32 via pure bit ops (exact)
__device__ __forceinline__ void bf2dec(unsigned v, float& a, float& b) {
    a = __int_as_float((int)(v << 16));
    b = __int_as_float((int)(v & 0xffff0000u));
}

// Pooled pyramids, PADDED layout: element (x,y) of image img lives at
// img*PW*PH + (y+5)*PW + (x+6). Pads are never written -> remain zero
// (device globals are zero-initialized), giving zero-padding for free.
__device__ __nv_bfloat162 g_s1[64 * PW1 * PH1];
__device__ __nv_bfloat162 g_s2[64 * PW2 * PH2];
__device__ double g_acc[3];   // zero-initialized at load; reset by finalize

// ---------------------------------------------------------------------------
// Phases 3-5 (exactly R7). Tile x-origin is x0-6: output col c taps smem
// cols c+1..c+11; pair (c0,c0+1) reads cols c0..c0+13 via 7 LDS.64.
// ---------------------------------------------------------------------------
__device__ __forceinline__ void phases345(
    __nv_bfloat162 (&sxy)[LDIM][SPITCH],
    ulonglong2 (&pAB)[LDIM][TILE],
    float (&red)[8],
    int tx, int ty, int tid, int sidx)
{
    u64 wp[11];
    #pragma unroll
    for (int k = 0; k < 11; k++) wp[k] = pack2(GWC[k], GWC[k]);

    // ---- horizontal blur: 672 items x 2 outputs ----
    #pragma unroll
    for (int it = 0; it < 3; it++) {
        const int i = tid + it * 256;
        if (i < 672) {
            const int r  = i >> 4;
            const int cb = i & 15;                       // pair base c0 = 2*cb
            const uint2* row64 = (const uint2*)&sxy[r][0];
            uint2 raw[7];
            #pragma unroll
            for (int m = 0; m < 7; m++)
                raw[m] = row64[cb + m];
            u64 hA0 = 0, hB0 = 0, hA1 = 0, hB1 = 0;
            #pragma unroll
            for (int n = 1; n <= 12; n++) {
                unsigned v = (n & 1) ? raw[n >> 1].y : raw[n >> 1].x;
                float a, b; bf2dec(v, a, b);
                u64 p  = pack2(a, b);
                u64 sq = mul2(p, p);
                if (n <= 11) {            // out0: weight w[n-1]
                    hA0 = fma2(p,  wp[n - 1], hA0);
                    hB0 = fma2(sq, wp[n - 1], hB0);
                }
                if (n >= 2) {             // out1: weight w[n-2]
                    hA1 = fma2(p,  wp[n - 2], hA1);
                    hB1 = fma2(sq, wp[n - 2], hB1);
                }
            }
            pAB[r][2 * cb]     = make_ulonglong2(hA0, hB0);
            pAB[r][2 * cb + 1] = make_ulonglong2(hA1, hB1);
        }
    }
    __syncthreads();

    // ---- vertical blur + SSIM: 4 output rows per thread, 1 col ----
    u64 mA[4] = {0, 0, 0, 0};   // (mu_u, mu_v)
    u64 mB[4] = {0, 0, 0, 0};   // (E[u^2], E[v^2])
    const int rbase = ty * 4;
    #pragma unroll
    for (int k = 0; k < 14; k++) {
        const int hr = rbase + k;
        ulonglong2 vab = pAB[hr][tx];          // LDS.128
        #pragma unroll
        for (int j = 0; j < 4; j++) {
            const int kk = k - j;
            if (kk >= 0 && kk < 11) {
                mA[j] = fma2(vab.x, wp[kk], mA[j]);
                mB[j] = fma2(vab.y, wp[kk], mB[j]);
            }
        }
    }

    float acc = 0.0f;
    #pragma unroll
    for (int j = 0; j < 4; j++) {
        u64 m2 = mul2(mA[j], mA[j]);           // (mu_u^2, mu_v^2)
        float m2u, m2v; unpack2(m2, m2u, m2v);
        float eu, ev;   unpack2(mB[j], eu, ev);
        float D1 = m2u - m2v;                  // = 4*mu1*mu2
        float S1 = m2u + m2v;                  // = 2*(mu1^2+mu2^2)
        float DE = eu - ev;                    // = 4*E[xy]
        float SE = eu + ev;                    // = 2*(E[x^2]+E[y^2])
        float num = (0.5f * D1 + C1_) * (0.5f * (DE - D1) + C2_);
        float den = (0.5f * S1 + C1_) * (0.5f * (SE - S1) + C2_);
        acc += __fdividef(num, den);
    }

    #pragma unroll
    for (int o = 16; o > 0; o >>= 1)
        acc += __shfl_down_sync(0xffffffffu, acc, o);
    if ((tid & 31) == 0) red[tid >> 5] = acc;
    __syncthreads();
    if (tid < 8) {
        float v = red[tid];
        #pragma unroll
        for (int o = 4; o > 0; o >>= 1)
            v += __shfl_down_sync(0xffu, v, o, 8);
        if (tid == 0) atomicAdd(&g_acc[sidx], (double)v);
    }
}

// ---------------------------------------------------------------------------
// Scale 0: fp32 global inputs -> (u,v) bf16x2 tile; writes BOTH pooled
// pyramids (padded layout); then SSIM.
// ---------------------------------------------------------------------------
__global__ __launch_bounds__(256, 7)
void ssim_scale0_kernel(const float* __restrict__ pin, const float* __restrict__ tin)
{
    __shared__ __nv_bfloat162 sxy[LDIM][SPITCH];
    __shared__ ulonglong2 pAB[LDIM][TILE];
    __shared__ float red[8];

    const int tx = threadIdx.x, ty = threadIdx.y;
    const int tid = ty * 32 + tx;
    const int x0 = blockIdx.x * TILE;
    const int y0 = blockIdx.y * TILE;
    const int H = 512, W = 512;
    const long imgBase = (long)blockIdx.z * H * W;

    const bool interior = (x0 >= 8) && (x0 + 40 <= W) &&
                          (y0 >= 8) && (y0 + 40 <= H);
    if (interior) {
        // 42 rows x 22 float2 loads (x origin x0-6, 8B aligned)
        const float* pb = pin + imgBase + (long)(y0 - 5) * W + (x0 - 6);
        const float* tb = tin + imgBase + (long)(y0 - 5) * W + (x0 - 6);
        #pragma unroll
        for (int it = 0; it < 4; it++) {
            const int i = tid + it * 256;
            if (i < 924) {
                const int r = i / 22, c2 = i - r * 22;
                float2 av = __ldg((const float2*)(pb + (long)r * W) + c2);
                float2 bv = __ldg((const float2*)(tb + (long)r * W) + c2);
                __nv_bfloat162 t0 = __floats2bfloat162_rn(av.x + bv.x, av.x - bv.x);
                __nv_bfloat162 t1 = __floats2bfloat162_rn(av.y + bv.y, av.y - bv.y);
                *(uint2*)&sxy[r][2 * c2] =
                    make_uint2(*(unsigned*)&t0, *(unsigned*)&t1);
            }
        }
    } else {
        #pragma unroll
        for (int i = tid; i < LDIM * SPITCH; i += 256) {
            int r = i / SPITCH, c = i - r * SPITCH;
            int gy = y0 + r - 5;
            int gx = x0 + c - 6;
            float a = 0.0f, b = 0.0f;
            if (gy >= 0 && gy < H && gx >= 0 && gx < W) {
                long off = imgBase + (long)gy * W + gx;
                a = __ldg(pin + off);
                b = __ldg(tin + off);
            }
            sxy[r][c] = __floats2bfloat162_rn(a + b, a - b);
        }
    }
    __syncthreads();

    // 2x2 pool -> g_s1 (padded layout; pooling is linear in (u,v))
    {
        const int pr = tid >> 4;
        const int pc = tid & 15;
        const int r = 5 + 2 * pr, c = 6 + 2 * pc;
        float u0, v0, u1, v1, u2, v2, u3, v3;
        bf2dec(*(const unsigned*)&sxy[r][c],         u0, v0);
        bf2dec(*(const unsigned*)&sxy[r][c + 1],     u1, v1);
        bf2dec(*(const unsigned*)&sxy[r + 1][c],     u2, v2);
        bf2dec(*(const unsigned*)&sxy[r + 1][c + 1], u3, v3);
        float u = 0.25f * (u0 + u1 + u2 + u3);
        float v = 0.25f * (v0 + v1 + v2 + v3);
        long poff = (long)blockIdx.z * (PW1 * PH1)
                  + (long)(y0 / 2 + pr + 5) * PW1 + (x0 / 2 + pc + 6);
        g_s1[poff] = __floats2bfloat162_rn(u, v);
    }
    // 4x4 pool -> g_s2 (padded layout; threads 0..63)
    if (tid < 64) {
        const int pr = tid >> 3;
        const int pc = tid & 7;
        const int r = 5 + 4 * pr, c = 6 + 4 * pc;
        float su = 0.f, sv = 0.f;
        #pragma unroll
        for (int dr = 0; dr < 4; dr++)
            #pragma unroll
            for (int dc = 0; dc < 4; dc++) {
                float u, v;
                bf2dec(*(const unsigned*)&sxy[r + dr][c + dc], u, v);
                su += u; sv += v;
            }
        long poff = (long)blockIdx.z * (PW2 * PH2)
                  + (long)(y0 / 4 + pr + 5) * PW2 + (x0 / 4 + pc + 6);
        g_s2[poff] = __floats2bfloat162_rn(su * 0.0625f, sv * 0.0625f);
    }

    phases345(sxy, pAB, red, tx, ty, tid, 0);
}

// ---------------------------------------------------------------------------
// Scales 1+2 merged: z < 64 -> scale1 (256x256), z >= 64 -> scale2 (128x128).
// Padded pyramids: tile origin (x0-6, y0-5) = padded element y0*PW + x0,
// so EVERY block uses the vectorized loader (no border branch).
// ---------------------------------------------------------------------------
__global__ __launch_bounds__(256, 7)
void ssim_small_kernel()
{
    __shared__ __nv_bfloat162 sxy[LDIM][SPITCH];
    __shared__ ulonglong2 pAB[LDIM][TILE];
    __shared__ float red[8];

    const int tx = threadIdx.x, ty = threadIdx.y;
    const int tid = ty * 32 + tx;
    const int z = blockIdx.z;

    const __nv_bfloat162* base;
    int pw, sidx;
    if (z < 64) {
        const int x0 = blockIdx.x * TILE;
        const int y0 = blockIdx.y * TILE;
        base = g_s1 + (long)z * (PW1 * PH1) + (long)y0 * PW1 + x0;
        pw = PW1; sidx = 1;
    } else {
        const int z2 = z - 64;
        const int img = z2 * 4 + ((blockIdx.y >> 2) << 1) + (blockIdx.x >> 2);
        const int x0 = (blockIdx.x & 3) * TILE;
        const int y0 = (blockIdx.y & 3) * TILE;
        base = g_s2 + (long)img * (PW2 * PH2) + (long)y0 * PW2 + x0;
        pw = PW2; sidx = 2;
    }

    // 42 rows x 22 uint2 loads; all addresses 8B-aligned (even indices).
    #pragma unroll
    for (int it = 0; it < 4; it++) {
        const int i = tid + it * 256;
        if (i < 924) {
            const int r = i / 22, c2 = i - r * 22;
            uint2 v = __ldg((const uint2*)(base + (long)r * pw) + c2);
            *(uint2*)&sxy[r][2 * c2] = v;
        }
    }
    __syncthreads();

    phases345(sxy, pAB, red, tx, ty, tid, sidx);
}

__global__ void finalize_kernel(float* __restrict__ out) {
    const double n0 = 64.0 * 512.0 * 512.0;
    const double n1 = 64.0 * 256.0 * 256.0;
    const double n2 = 64.0 * 128.0 * 128.0;
    double ms = 0.5 * (g_acc[0] / n0) + 0.3 * (g_acc[1] / n1) + 0.2 * (g_acc[2] / n2);
    out[0] = (float)(1.0 - ms);
    // reset for the next graph replay (globals start zeroed at module load)
    g_acc[0] = 0.0; g_acc[1] = 0.0; g_acc[2] = 0.0;
}

extern "C" void kernel_launch(void* const* d_in, const int* in_sizes, int n_in,
                              void* d_out, int out_size)
{
    const float* pred = (const float*)d_in[0];
    const float* targ = (const float*)d_in[1];
    float* out = (float*)d_out;

    dim3 blk(32, 8);
    ssim_scale0_kernel<<<dim3(16, 16, 64), blk>>>(pred, targ);
    ssim_small_kernel<<<dim3(8, 8, 80), blk>>>();
    finalize_kernel<<<1, 1>>>(out);
}

// round 15
// speedup vs baseline: 1.0997x; 1.0310x over previous
#include <cuda_runtime.h>
#include <cuda_bf16.h>

// ---------------------------------------------------------------------------
// MS-SSIM loss, 3 scales, 11x11 separable Gaussian (sigma=1.5), zero padding.
// R14: R13 champion + (a) direct bf16x2 -> packed fp32x2 decode (bf2pack: one
//      shl + one and into the register pair, no repack) in phase 3 and pools,
//      (b) vectorized scale-0 border loader (range-predicated float2 loads
//      instead of 1848 scalar iterations).
// ---------------------------------------------------------------------------

#define TILE   32
#define HALO   5
#define LDIM   42            // TILE + 2*HALO
#define SPITCH 44            // raw tile pitch (bf16x2 units), origin x0-6

// padded pyramid dims: left pad 6, right pad 8, top/bottom pad 5
#define PW1 270
#define PH1 266
#define PW2 142
#define PH2 138

__device__ constexpr float GWC[11] = {
    0.00102838f, 0.00759875f, 0.03600077f, 0.10936069f, 0.21300553f,
    0.26601173f, 0.21300553f, 0.10936069f, 0.03600077f, 0.00759875f,
    0.00102838f
};

#define C1_ 0.0001f
#define C2_ 0.0009f

typedef unsigned long long u64;

__device__ __forceinline__ u64 pack2(float a, float b) {
    u64 r; asm("mov.b64 %0, {%1, %2};" : "=l"(r) : "f"(a), "f"(b)); return r;
}
__device__ __forceinline__ void unpack2(u64 v, float& a, float& b) {
    asm("mov.b64 {%0, %1}, %2;" : "=f"(a), "=f"(b) : "l"(v));
}
__device__ __forceinline__ u64 fma2(u64 a, u64 b, u64 c) {
    u64 d; asm("fma.rn.f32x2 %0, %1, %2, %3;" : "=l"(d) : "l"(a), "l"(b), "l"(c)); return d;
}
__device__ __forceinline__ u64 mul2(u64 a, u64 b) {
    u64 d; asm("mul.rn.f32x2 %0, %1, %2;" : "=l"(d) : "l"(a), "l"(b)); return d;
}
__device__ __forceinline__ u64 add2(u64 a, u64 b) {
    u64 d; asm("add.rn.f32x2 %0, %1, %2;" : "=l"(d) : "l"(a), "l"(b)); return d;
}
// bf16x2 (u,v) -> packed fp32x2 u64 directly: lo = v<<16 (u), hi = v&~0xffff (v).
__device__ __forceinline__ u64 bf2pack(unsigned v) {
    u64 r;
    asm("{\n\t"
        ".reg .b32 lo, hi;\n\t"
        "shl.b32 lo, %1, 16;\n\t"
        "and.b32 hi, %1, 0xffff0000;\n\t"
        "mov.b64 %0, {lo, hi};\n\t"
        "}"
        : "=l"(r) : "r"(v));
    return r;
}

// Pooled pyramids, PADDED layout: element (x,y) of image img lives at
// img*PW*PH + (y+5)*PW + (x+6). Pads are never written -> remain zero
// (device globals are zero-initialized), giving zero-padding for free.
__device__ __nv_bfloat162 g_s1[64 * PW1 * PH1];
__device__ __nv_bfloat162 g_s2[64 * PW2 * PH2];
__device__ double g_acc[3];   // zero-initialized at load; reset by finalize

// ---------------------------------------------------------------------------
// Phases 3-5 (R7 structure). Tile x-origin is x0-6: output col c taps smem
// cols c+1..c+11; pair (c0,c0+1) reads cols c0..c0+13 via 7 LDS.64.
// ---------------------------------------------------------------------------
__device__ __forceinline__ void phases345(
    __nv_bfloat162 (&sxy)[LDIM][SPITCH],
    ulonglong2 (&pAB)[LDIM][TILE],
    float (&red)[8],
    int tx, int ty, int tid, int sidx)
{
    u64 wp[11];
    #pragma unroll
    for (int k = 0; k < 11; k++) wp[k] = pack2(GWC[k], GWC[k]);

    // ---- horizontal blur: 672 items x 2 outputs ----
    #pragma unroll
    for (int it = 0; it < 3; it++) {
        const int i = tid + it * 256;
        if (i < 672) {
            const int r  = i >> 4;
            const int cb = i & 15;                       // pair base c0 = 2*cb
            const uint2* row64 = (const uint2*)&sxy[r][0];
            uint2 raw[7];
            #pragma unroll
            for (int m = 0; m < 7; m++)
                raw[m] = row64[cb + m];
            u64 hA0 = 0, hB0 = 0, hA1 = 0, hB1 = 0;
            #pragma unroll
            for (int n = 1; n <= 12; n++) {
                unsigned v = (n & 1) ? raw[n >> 1].y : raw[n >> 1].x;
                u64 p  = bf2pack(v);
                u64 sq = mul2(p, p);
                if (n <= 11) {            // out0: weight w[n-1]
                    hA0 = fma2(p,  wp[n - 1], hA0);
                    hB0 = fma2(sq, wp[n - 1], hB0);
                }
                if (n >= 2) {             // out1: weight w[n-2]
                    hA1 = fma2(p,  wp[n - 2], hA1);
                    hB1 = fma2(sq, wp[n - 2], hB1);
                }
            }
            pAB[r][2 * cb]     = make_ulonglong2(hA0, hB0);
            pAB[r][2 * cb + 1] = make_ulonglong2(hA1, hB1);
        }
    }
    __syncthreads();

    // ---- vertical blur + SSIM: 4 output rows per thread, 1 col ----
    u64 mA[4] = {0, 0, 0, 0};   // (mu_u, mu_v)
    u64 mB[4] = {0, 0, 0, 0};   // (E[u^2], E[v^2])
    const int rbase = ty * 4;
    #pragma unroll
    for (int k = 0; k < 14; k++) {
        const int hr = rbase + k;
        ulonglong2 vab = pAB[hr][tx];          // LDS.128
        #pragma unroll
        for (int j = 0; j < 4; j++) {
            const int kk = k - j;
            if (kk >= 0 && kk < 11) {
                mA[j] = fma2(vab.x, wp[kk], mA[j]);
                mB[j] = fma2(vab.y, wp[kk], mB[j]);
            }
        }
    }

    float acc = 0.0f;
    #pragma unroll
    for (int j = 0; j < 4; j++) {
        u64 m2 = mul2(mA[j], mA[j]);           // (mu_u^2, mu_v^2)
        float m2u, m2v; unpack2(m2, m2u, m2v);
        float eu, ev;   unpack2(mB[j], eu, ev);
        float D1 = m2u - m2v;                  // = 4*mu1*mu2
        float S1 = m2u + m2v;                  // = 2*(mu1^2+mu2^2)
        float DE = eu - ev;                    // = 4*E[xy]
        float SE = eu + ev;                    // = 2*(E[x^2]+E[y^2])
        float num = (0.5f * D1 + C1_) * (0.5f * (DE - D1) + C2_);
        float den = (0.5f * S1 + C1_) * (0.5f * (SE - S1) + C2_);
        acc += __fdividef(num, den);
    }

    #pragma unroll
    for (int o = 16; o > 0; o >>= 1)
        acc += __shfl_down_sync(0xffffffffu, acc, o);
    if ((tid & 31) == 0) red[tid >> 5] = acc;
    __syncthreads();
    if (tid < 8) {
        float v = red[tid];
        #pragma unroll
        for (int o = 4; o > 0; o >>= 1)
            v += __shfl_down_sync(0xffu, v, o, 8);
        if (tid == 0) atomicAdd(&g_acc[sidx], (double)v);
    }
}

// ---------------------------------------------------------------------------
// Scale 0: fp32 global inputs -> (u,v) bf16x2 tile; writes BOTH pooled
// pyramids (padded layout); then SSIM. Border blocks use the vectorized
// loader with row/column range predicates (no scalar path).
// ---------------------------------------------------------------------------
__global__ __launch_bounds__(256, 7)
void ssim_scale0_kernel(const float* __restrict__ pin, const float* __restrict__ tin)
{
    __shared__ __nv_bfloat162 sxy[LDIM][SPITCH];
    __shared__ ulonglong2 pAB[LDIM][TILE];
    __shared__ float red[8];

    const int tx = threadIdx.x, ty = threadIdx.y;
    const int tid = ty * 32 + tx;
    const int x0 = blockIdx.x * TILE;
    const int y0 = blockIdx.y * TILE;
    const int H = 512, W = 512;
    const long imgBase = (long)blockIdx.z * H * W;

    const bool interior = (x0 >= 8) && (x0 + 40 <= W) &&
                          (y0 >= 8) && (y0 + 40 <= H);
    const float* pb = pin + imgBase + (long)(y0 - 5) * W + (x0 - 6);
    const float* tb = tin + imgBase + (long)(y0 - 5) * W + (x0 - 6);
    if (interior) {
        // 42 rows x 22 float2 loads (x origin x0-6, 8B aligned)
        #pragma unroll
        for (int it = 0; it < 4; it++) {
            const int i = tid + it * 256;
            if (i < 924) {
                const int r = i / 22, c2 = i - r * 22;
                float2 av = __ldg((const float2*)(pb + (long)r * W) + c2);
                float2 bv = __ldg((const float2*)(tb + (long)r * W) + c2);
                __nv_bfloat162 t0 = __floats2bfloat162_rn(av.x + bv.x, av.x - bv.x);
                __nv_bfloat162 t1 = __floats2bfloat162_rn(av.y + bv.y, av.y - bv.y);
                *(uint2*)&sxy[r][2 * c2] =
                    make_uint2(*(unsigned*)&t0, *(unsigned*)&t1);
            }
        }
    } else {
        // Border: same vectorized loads, range-predicated.
        // Left block (x0==0): c2 0..2 cover gx -6..-1 -> zero.
        // Right block (x0==480): c2 19..21 cover gx 512..517 -> zero.
        const int c2lo = (x0 == 0) ? 3 : 0;
        const int c2hi = (x0 + TILE == W) ? 19 : 22;
        #pragma unroll
        for (int it = 0; it < 4; it++) {
            const int i = tid + it * 256;
            if (i < 924) {
                const int r = i / 22, c2 = i - r * 22;
                const int gy = y0 + r - 5;
                const bool ok = (gy >= 0) && (gy < H) &&
                                (c2 >= c2lo) && (c2 < c2hi);
                float2 av = make_float2(0.f, 0.f);
                float2 bv = make_float2(0.f, 0.f);
                if (ok) {
                    av = __ldg((const float2*)(pb + (long)r * W) + c2);
                    bv = __ldg((const float2*)(tb + (long)r * W) + c2);
                }
                __nv_bfloat162 t0 = __floats2bfloat162_rn(av.x + bv.x, av.x - bv.x);
                __nv_bfloat162 t1 = __floats2bfloat162_rn(av.y + bv.y, av.y - bv.y);
                *(uint2*)&sxy[r][2 * c2] =
                    make_uint2(*(unsigned*)&t0, *(unsigned*)&t1);
            }
        }
    }
    __syncthreads();

    const u64 quarter2 = pack2(0.25f, 0.25f);

    // 2x2 pool -> g_s1 (padded layout; pooling is linear in (u,v)), packed
    {
        const int pr = tid >> 4;
        const int pc = tid & 15;
        const int r = 5 + 2 * pr, c = 6 + 2 * pc;
        u64 s = add2(add2(bf2pack(*(const unsigned*)&sxy[r][c]),
                          bf2pack(*(const unsigned*)&sxy[r][c + 1])),
                     add2(bf2pack(*(const unsigned*)&sxy[r + 1][c]),
                          bf2pack(*(const unsigned*)&sxy[r + 1][c + 1])));
        s = mul2(s, quarter2);
        float u, v; unpack2(s, u, v);
        long poff = (long)blockIdx.z * (PW1 * PH1)
                  + (long)(y0 / 2 + pr + 5) * PW1 + (x0 / 2 + pc + 6);
        g_s1[poff] = __floats2bfloat162_rn(u, v);
    }
    // 4x4 pool -> g_s2 (padded layout; threads 0..63), packed
    if (tid < 64) {
        const int pr = tid >> 3;
        const int pc = tid & 7;
        const int r = 5 + 4 * pr, c = 6 + 4 * pc;
        u64 s = 0;
        #pragma unroll
        for (int dr = 0; dr < 4; dr++) {
            u64 rs = add2(add2(bf2pack(*(const unsigned*)&sxy[r + dr][c]),
                               bf2pack(*(const unsigned*)&sxy[r + dr][c + 1])),
                          add2(bf2pack(*(const unsigned*)&sxy[r + dr][c + 2]),
                               bf2pack(*(const unsigned*)&sxy[r + dr][c + 3])));
            s = (dr == 0) ? rs : add2(s, rs);
        }
        s = mul2(s, mul2(quarter2, quarter2));
        float u, v; unpack2(s, u, v);
        long poff = (long)blockIdx.z * (PW2 * PH2)
                  + (long)(y0 / 4 + pr + 5) * PW2 + (x0 / 4 + pc + 6);
        g_s2[poff] = __floats2bfloat162_rn(u, v);
    }

    phases345(sxy, pAB, red, tx, ty, tid, 0);
}

// ---------------------------------------------------------------------------
// Scales 1+2 merged: z < 64 -> scale1 (256x256), z >= 64 -> scale2 (128x128).
// Padded pyramids: tile origin (x0-6, y0-5) = padded element y0*PW + x0,
// so EVERY block uses the vectorized loader (no border branch).
// ---------------------------------------------------------------------------
__global__ __launch_bounds__(256, 7)
void ssim_small_kernel()
{
    __shared__ __nv_bfloat162 sxy[LDIM][SPITCH];
    __shared__ ulonglong2 pAB[LDIM][TILE];
    __shared__ float red[8];

    const int tx = threadIdx.x, ty = threadIdx.y;
    const int tid = ty * 32 + tx;
    const int z = blockIdx.z;

    const __nv_bfloat162* base;
    int pw, sidx;
    if (z < 64) {
        const int x0 = blockIdx.x * TILE;
        const int y0 = blockIdx.y * TILE;
        base = g_s1 + (long)z * (PW1 * PH1) + (long)y0 * PW1 + x0;
        pw = PW1; sidx = 1;
    } else {
        const int z2 = z - 64;
        const int img = z2 * 4 + ((blockIdx.y >> 2) << 1) + (blockIdx.x >> 2);
        const int x0 = (blockIdx.x & 3) * TILE;
        const int y0 = (blockIdx.y & 3) * TILE;
        base = g_s2 + (long)img * (PW2 * PH2) + (long)y0 * PW2 + x0;
        pw = PW2; sidx = 2;
    }

    // 42 rows x 22 uint2 loads; all addresses 8B-aligned (even indices).
    #pragma unroll
    for (int it = 0; it < 4; it++) {
        const int i = tid + it * 256;
        if (i < 924) {
            const int r = i / 22, c2 = i - r * 22;
            uint2 v = __ldg((const uint2*)(base + (long)r * pw) + c2);
            *(uint2*)&sxy[r][2 * c2] = v;
        }
    }
    __syncthreads();

    phases345(sxy, pAB, red, tx, ty, tid, sidx);
}

__global__ void finalize_kernel(float* __restrict__ out) {
    const double n0 = 64.0 * 512.0 * 512.0;
    const double n1 = 64.0 * 256.0 * 256.0;
    const double n2 = 64.0 * 128.0 * 128.0;
    double ms = 0.5 * (g_acc[0] / n0) + 0.3 * (g_acc[1] / n1) + 0.2 * (g_acc[2] / n2);
    out[0] = (float)(1.0 - ms);
    // reset for the next graph replay (globals start zeroed at module load)
    g_acc[0] = 0.0; g_acc[1] = 0.0; g_acc[2] = 0.0;
}

extern "C" void kernel_launch(void* const* d_in, const int* in_sizes, int n_in,
                              void* d_out, int out_size)
{
    const float* pred = (const float*)d_in[0];
    const float* targ = (const float*)d_in[1];
    float* out = (float*)d_out;

    dim3 blk(32, 8);
    ssim_scale0_kernel<<<dim3(16, 16, 64), blk>>>(pred, targ);
    ssim_small_kernel<<<dim3(8, 8, 80), blk>>>();
    finalize_kernel<<<1, 1>>>(out);
}

// round 16
// speedup vs baseline: 1.1121x; 1.0113x over previous
#include <cuda_runtime.h>
#include <cuda_bf16.h>

// ---------------------------------------------------------------------------
// MS-SSIM loss, 3 scales, 11x11 separable Gaussian (sigma=1.5), zero padding.
// R15: R14 hot loops frozen; scale-0 tile 32x64 with 512 threads and dynamic
//      smem (50.9KB, 4 blocks/SM = 64 warps): halo overhead 1.31x -> 1.16x,
//      half the blocks (pool/reduction overhead halved). Small kernel
//      unchanged (templated phases).
// ---------------------------------------------------------------------------

#define TILE   32
#define HALO   5
#define SPITCH 44            // raw tile pitch (bf16x2 units), origin x0-6

// padded pyramid dims: left pad 6, right pad 8, top/bottom pad 5
#define PW1 270
#define PH1 266
#define PW2 142
#define PH2 138

// scale-0 tall tile
#define TY0 64
#define LY0 74

__device__ constexpr float GWC[11] = {
    0.00102838f, 0.00759875f, 0.03600077f, 0.10936069f, 0.21300553f,
    0.26601173f, 0.21300553f, 0.10936069f, 0.03600077f, 0.00759875f,
    0.00102838f
};

#define C1_ 0.0001f
#define C2_ 0.0009f

typedef unsigned long long u64;

__device__ __forceinline__ u64 pack2(float a, float b) {
    u64 r; asm("mov.b64 %0, {%1, %2};" : "=l"(r) : "f"(a), "f"(b)); return r;
}
__device__ __forceinline__ void unpack2(u64 v, float& a, float& b) {
    asm("mov.b64 {%0, %1}, %2;" : "=f"(a), "=f"(b) : "l"(v));
}
__device__ __forceinline__ u64 fma2(u64 a, u64 b, u64 c) {
    u64 d; asm("fma.rn.f32x2 %0, %1, %2, %3;" : "=l"(d) : "l"(a), "l"(b), "l"(c)); return d;
}
__device__ __forceinline__ u64 mul2(u64 a, u64 b) {
    u64 d; asm("mul.rn.f32x2 %0, %1, %2;" : "=l"(d) : "l"(a), "l"(b)); return d;
}
__device__ __forceinline__ u64 add2(u64 a, u64 b) {
    u64 d; asm("add.rn.f32x2 %0, %1, %2;" : "=l"(d) : "l"(a), "l"(b)); return d;
}
// bf16x2 (u,v) -> packed fp32x2 u64 directly: lo = v<<16 (u), hi = v&~0xffff (v).
__device__ __forceinline__ u64 bf2pack(unsigned v) {
    u64 r;
    asm("{\n\t"
        ".reg .b32 lo, hi;\n\t"
        "shl.b32 lo, %1, 16;\n\t"
        "and.b32 hi, %1, 0xffff0000;\n\t"
        "mov.b64 %0, {lo, hi};\n\t"
        "}"
        : "=l"(r) : "r"(v));
    return r;
}

// Pooled pyramids, PADDED layout: element (x,y) of image img lives at
// img*PW*PH + (y+5)*PW + (x+6). Pads are never written -> remain zero.
__device__ __nv_bfloat162 g_s1[64 * PW1 * PH1];
__device__ __nv_bfloat162 g_s2[64 * PW2 * PH2];
__device__ double g_acc[3];   // zero-initialized at load; reset by finalize

// ---------------------------------------------------------------------------
// Phases 3-5, templated on tile rows (LY) and thread count (NT).
// Tile x-origin is x0-6: output col c taps smem cols c+1..c+11; pair
// (c0,c0+1) reads cols c0..c0+13 via 7 LDS.64.
// ---------------------------------------------------------------------------
template <int LY, int NT>
__device__ __forceinline__ void phases345(
    __nv_bfloat162 (*sxy)[SPITCH],
    ulonglong2 (*pAB)[TILE],
    float* red,
    int tx, int ty, int tid, int sidx)
{
    constexpr int NW = NT / 32;
    u64 wp[11];
    #pragma unroll
    for (int k = 0; k < 11; k++) wp[k] = pack2(GWC[k], GWC[k]);

    // ---- horizontal blur: LY*16 items x 2 outputs ----
    #pragma unroll
    for (int i = tid; i < LY * 16; i += NT) {
        const int r  = i >> 4;
        const int cb = i & 15;                       // pair base c0 = 2*cb
        const uint2* row64 = (const uint2*)&sxy[r][0];
        uint2 raw[7];
        #pragma unroll
        for (int m = 0; m < 7; m++)
            raw[m] = row64[cb + m];
        u64 hA0 = 0, hB0 = 0, hA1 = 0, hB1 = 0;
        #pragma unroll
        for (int n = 1; n <= 12; n++) {
            unsigned v = (n & 1) ? raw[n >> 1].y : raw[n >> 1].x;
            u64 p  = bf2pack(v);
            u64 sq = mul2(p, p);
            if (n <= 11) {            // out0: weight w[n-1]
                hA0 = fma2(p,  wp[n - 1], hA0);
                hB0 = fma2(sq, wp[n - 1], hB0);
            }
            if (n >= 2) {             // out1: weight w[n-2]
                hA1 = fma2(p,  wp[n - 2], hA1);
                hB1 = fma2(sq, wp[n - 2], hB1);
            }
        }
        pAB[r][2 * cb]     = make_ulonglong2(hA0, hB0);
        pAB[r][2 * cb + 1] = make_ulonglong2(hA1, hB1);
    }
    __syncthreads();

    // ---- vertical blur + SSIM: 4 output rows per thread, 1 col ----
    u64 mA[4] = {0, 0, 0, 0};   // (mu_u, mu_v)
    u64 mB[4] = {0, 0, 0, 0};   // (E[u^2], E[v^2])
    const int rbase = ty * 4;
    #pragma unroll
    for (int k = 0; k < 14; k++) {
        const int hr = rbase + k;
        ulonglong2 vab = pAB[hr][tx];          // LDS.128
        #pragma unroll
        for (int j = 0; j < 4; j++) {
            const int kk = k - j;
            if (kk >= 0 && kk < 11) {
                mA[j] = fma2(vab.x, wp[kk], mA[j]);
                mB[j] = fma2(vab.y, wp[kk], mB[j]);
            }
        }
    }

    float acc = 0.0f;
    #pragma unroll
    for (int j = 0; j < 4; j++) {
        u64 m2 = mul2(mA[j], mA[j]);           // (mu_u^2, mu_v^2)
        float m2u, m2v; unpack2(m2, m2u, m2v);
        float eu, ev;   unpack2(mB[j], eu, ev);
        float D1 = m2u - m2v;                  // = 4*mu1*mu2
        float S1 = m2u + m2v;                  // = 2*(mu1^2+mu2^2)
        float DE = eu - ev;                    // = 4*E[xy]
        float SE = eu + ev;                    // = 2*(E[x^2]+E[y^2])
        float num = (0.5f * D1 + C1_) * (0.5f * (DE - D1) + C2_);
        float den = (0.5f * S1 + C1_) * (0.5f * (SE - S1) + C2_);
        acc += __fdividef(num, den);
    }

    #pragma unroll
    for (int o = 16; o > 0; o >>= 1)
        acc += __shfl_down_sync(0xffffffffu, acc, o);
    if ((tid & 31) == 0) red[tid >> 5] = acc;
    __syncthreads();
    if (tid < NW) {
        float v = red[tid];
        #pragma unroll
        for (int o = NW / 2; o > 0; o >>= 1)
            v += __shfl_down_sync((unsigned)((1ull << NW) - 1ull), v, o, NW);
        if (tid == 0) atomicAdd(&g_acc[sidx], (double)v);
    }
}

// ---------------------------------------------------------------------------
// Scale 0: 32x64 tile, 512 threads, dynamic smem. fp32 inputs -> (u,v)
// bf16x2 tile; writes BOTH pooled pyramids (padded layout); then SSIM.
// ---------------------------------------------------------------------------
static constexpr int SMEM0_PAB = LY0 * SPITCH * 4;               // 13024
static constexpr int SMEM0_RED = SMEM0_PAB + LY0 * TILE * 16;    // 50912
static constexpr int SMEM0_TOTAL = SMEM0_RED + 64;               // 50976

__global__ __launch_bounds__(512, 4)
void ssim_scale0_kernel(const float* __restrict__ pin, const float* __restrict__ tin)
{
    extern __shared__ char smem[];
    __nv_bfloat162 (*sxy)[SPITCH] =
        reinterpret_cast<__nv_bfloat162(*)[SPITCH]>(smem);
    ulonglong2 (*pAB)[TILE] =
        reinterpret_cast<ulonglong2(*)[TILE]>(smem + SMEM0_PAB);
    float* red = reinterpret_cast<float*>(smem + SMEM0_RED);

    const int tx = threadIdx.x, ty = threadIdx.y;
    const int tid = ty * 32 + tx;
    const int x0 = blockIdx.x * TILE;
    const int y0 = blockIdx.y * TY0;
    const int H = 512, W = 512;
    const long imgBase = (long)blockIdx.z * H * W;

    const bool interior = (x0 >= 8) && (x0 + 40 <= W) &&
                          (y0 >= 8) && (y0 + TY0 + 8 <= H);
    const float* pb = pin + imgBase + (long)(y0 - 5) * W + (x0 - 6);
    const float* tb = tin + imgBase + (long)(y0 - 5) * W + (x0 - 6);
    if (interior) {
        // 74 rows x 22 float2 loads (x origin x0-6, 8B aligned)
        #pragma unroll
        for (int i = tid; i < LY0 * 22; i += 512) {
            const int r = i / 22, c2 = i - r * 22;
            float2 av = __ldg((const float2*)(pb + (long)r * W) + c2);
            float2 bv = __ldg((const float2*)(tb + (long)r * W) + c2);
            __nv_bfloat162 t0 = __floats2bfloat162_rn(av.x + bv.x, av.x - bv.x);
            __nv_bfloat162 t1 = __floats2bfloat162_rn(av.y + bv.y, av.y - bv.y);
            *(uint2*)&sxy[r][2 * c2] =
                make_uint2(*(unsigned*)&t0, *(unsigned*)&t1);
        }
    } else {
        // Border: same vectorized loads, range-predicated.
        const int c2lo = (x0 == 0) ? 3 : 0;
        const int c2hi = (x0 + TILE == W) ? 19 : 22;
        #pragma unroll
        for (int i = tid; i < LY0 * 22; i += 512) {
            const int r = i / 22, c2 = i - r * 22;
            const int gy = y0 + r - 5;
            const bool ok = (gy >= 0) && (gy < H) &&
                            (c2 >= c2lo) && (c2 < c2hi);
            float2 av = make_float2(0.f, 0.f);
            float2 bv = make_float2(0.f, 0.f);
            if (ok) {
                av = __ldg((const float2*)(pb + (long)r * W) + c2);
                bv = __ldg((const float2*)(tb + (long)r * W) + c2);
            }
            __nv_bfloat162 t0 = __floats2bfloat162_rn(av.x + bv.x, av.x - bv.x);
            __nv_bfloat162 t1 = __floats2bfloat162_rn(av.y + bv.y, av.y - bv.y);
            *(uint2*)&sxy[r][2 * c2] =
                make_uint2(*(unsigned*)&t0, *(unsigned*)&t1);
        }
    }
    __syncthreads();

    const u64 quarter2 = pack2(0.25f, 0.25f);

    // 2x2 pool -> g_s1: 32 rows x 16 cols = 512 outputs, one per thread
    {
        const int pr = tid >> 4;            // 0..31
        const int pc = tid & 15;            // 0..15
        const int r = 5 + 2 * pr, c = 6 + 2 * pc;
        u64 s = add2(add2(bf2pack(*(const unsigned*)&sxy[r][c]),
                          bf2pack(*(const unsigned*)&sxy[r][c + 1])),
                     add2(bf2pack(*(const unsigned*)&sxy[r + 1][c]),
                          bf2pack(*(const unsigned*)&sxy[r + 1][c + 1])));
        s = mul2(s, quarter2);
        float u, v; unpack2(s, u, v);
        long poff = (long)blockIdx.z * (PW1 * PH1)
                  + (long)(y0 / 2 + pr + 5) * PW1 + (x0 / 2 + pc + 6);
        g_s1[poff] = __floats2bfloat162_rn(u, v);
    }
    // 4x4 pool -> g_s2: 16 rows x 8 cols = 128 outputs (threads 0..127)
    if (tid < 128) {
        const int pr = tid >> 3;            // 0..15
        const int pc = tid & 7;             // 0..7
        const int r = 5 + 4 * pr, c = 6 + 4 * pc;
        u64 s = 0;
        #pragma unroll
        for (int dr = 0; dr < 4; dr++) {
            u64 rs = add2(add2(bf2pack(*(const unsigned*)&sxy[r + dr][c]),
                               bf2pack(*(const unsigned*)&sxy[r + dr][c + 1])),
                          add2(bf2pack(*(const unsigned*)&sxy[r + dr][c + 2]),
                               bf2pack(*(const unsigned*)&sxy[r + dr][c + 3])));
            s = (dr == 0) ? rs : add2(s, rs);
        }
        s = mul2(s, mul2(quarter2, quarter2));
        float u, v; unpack2(s, u, v);
        long poff = (long)blockIdx.z * (PW2 * PH2)
                  + (long)(y0 / 4 + pr + 5) * PW2 + (x0 / 4 + pc + 6);
        g_s2[poff] = __floats2bfloat162_rn(u, v);
    }

    phases345<LY0, 512>(sxy, pAB, red, tx, ty, tid, 0);
}

// ---------------------------------------------------------------------------
// Scales 1+2 merged: z < 64 -> scale1 (256x256), z >= 64 -> scale2 (128x128).
// Padded pyramids: every block uses the vectorized loader (no border branch).
// ---------------------------------------------------------------------------
__global__ __launch_bounds__(256, 7)
void ssim_small_kernel()
{
    __shared__ __nv_bfloat162 sxy[42][SPITCH];
    __shared__ ulonglong2 pAB[42][TILE];
    __shared__ float red[8];

    const int tx = threadIdx.x, ty = threadIdx.y;
    const int tid = ty * 32 + tx;
    const int z = blockIdx.z;

    const __nv_bfloat162* base;
    int pw, sidx;
    if (z < 64) {
        const int x0 = blockIdx.x * TILE;
        const int y0 = blockIdx.y * TILE;
        base = g_s1 + (long)z * (PW1 * PH1) + (long)y0 * PW1 + x0;
        pw = PW1; sidx = 1;
    } else {
        const int z2 = z - 64;
        const int img = z2 * 4 + ((blockIdx.y >> 2) << 1) + (blockIdx.x >> 2);
        const int x0 = (blockIdx.x & 3) * TILE;
        const int y0 = (blockIdx.y & 3) * TILE;
        base = g_s2 + (long)img * (PW2 * PH2) + (long)y0 * PW2 + x0;
        pw = PW2; sidx = 2;
    }

    // 42 rows x 22 uint2 loads; all addresses 8B-aligned (even indices).
    #pragma unroll
    for (int it = 0; it < 4; it++) {
        const int i = tid + it * 256;
        if (i < 924) {
            const int r = i / 22, c2 = i - r * 22;
            uint2 v = __ldg((const uint2*)(base + (long)r * pw) + c2);
            *(uint2*)&sxy[r][2 * c2] = v;
        }
    }
    __syncthreads();

    phases345<42, 256>(sxy, pAB, red, tx, ty, tid, sidx);
}

__global__ void finalize_kernel(float* __restrict__ out) {
    const double n0 = 64.0 * 512.0 * 512.0;
    const double n1 = 64.0 * 256.0 * 256.0;
    const double n2 = 64.0 * 128.0 * 128.0;
    double ms = 0.5 * (g_acc[0] / n0) + 0.3 * (g_acc[1] / n1) + 0.2 * (g_acc[2] / n2);
    out[0] = (float)(1.0 - ms);
    // reset for the next graph replay (globals start zeroed at module load)
    g_acc[0] = 0.0; g_acc[1] = 0.0; g_acc[2] = 0.0;
}

extern "C" void kernel_launch(void* const* d_in, const int* in_sizes, int n_in,
                              void* d_out, int out_size)
{
    const float* pred = (const float*)d_in[0];
    const float* targ = (const float*)d_in[1];
    float* out = (float*)d_out;

    cudaFuncSetAttribute(ssim_scale0_kernel,
                         cudaFuncAttributeMaxDynamicSharedMemorySize,
                         SMEM0_TOTAL);

    ssim_scale0_kernel<<<dim3(16, 8, 64), dim3(32, 16), SMEM0_TOTAL>>>(pred, targ);
    ssim_small_kernel<<<dim3(8, 8, 80), dim3(32, 8)>>>();
    finalize_kernel<<<1, 1>>>(out);
}